// round 2
// baseline (speedup 1.0000x reference)
#include <cuda_runtime.h>
#include <math.h>

// Problem constants
#define BN_TOT 8192          // B*H*W*T = 4*16*16*8
#define NTOK   5             // 3 (s2) + 2 (s1)
#define ROWS   40960         // BN_TOT * NTOK
#define DDIM   768
#define ADIM   256
#define NHEAD  8
#define HD     32
#define OUT_MAIN (BN_TOT * DDIM)   // 6291456

// Scratch (device-global: allocation-guard safe)
__device__ float g_X[ROWS * ADIM];
__device__ float g_K[ROWS * ADIM];
__device__ float g_V[ROWS * ADIM];
__device__ float g_CTX[BN_TOT * ADIM];
__device__ int   g_has[BN_TOT];

// ---------------------------------------------------------------------------
// Generic SGEMM:  C[M,Nn] = A[M,Kk] @ W[Nn,Kk]^T + bias[Nn]
// GATHER: A rows gathered from s2/s1 token tensors (concat along bandset axis)
// EPI_HAS: zero row if !has[row]
// Tiles: BM=64, BN=64, BK=16; 256 threads; 4x4 microtile.
// ---------------------------------------------------------------------------
template<bool GATHER, bool EPI_HAS>
__global__ __launch_bounds__(256)
void sgemm_tn(const float* __restrict__ A,
              const float* __restrict__ s2,
              const float* __restrict__ s1,
              const float* __restrict__ W,
              const float* __restrict__ bias,
              const int*   __restrict__ has,
              float*       __restrict__ C,
              int M, int Nn, int Kk)
{
    __shared__ float As[16][68];
    __shared__ float Bs[16][68];

    const int t     = threadIdx.x;
    const int mBase = blockIdx.y * 64;
    const int nBase = blockIdx.x * 64;

    // load-role indices: each thread loads one float4 of A and one of W per K-step
    const int arow = t >> 2;          // 0..63
    const int acol = (t & 3) * 4;     // 0,4,8,12

    const float* aptr;
    {
        const int grow = mBase + arow;
        if (GATHER) {
            const int bn = grow / NTOK;
            const int nn = grow - bn * NTOK;
            aptr = (nn < 3) ? (s2 + (size_t)(bn * 3 + nn) * DDIM)
                            : (s1 + (size_t)(bn * 2 + (nn - 3)) * DDIM);
        } else {
            aptr = A + (size_t)grow * Kk;
        }
    }
    const float* bptr = W + (size_t)(nBase + arow) * Kk;

    // compute-role indices
    const int tx = t & 15;            // column group
    const int ty = t >> 4;            // row group

    float acc[4][4] = {};

    for (int k0 = 0; k0 < Kk; k0 += 16) {
        const float4 av = *(const float4*)(aptr + k0 + acol);
        const float4 bv = *(const float4*)(bptr + k0 + acol);
        __syncthreads();
        As[acol + 0][arow] = av.x; As[acol + 1][arow] = av.y;
        As[acol + 2][arow] = av.z; As[acol + 3][arow] = av.w;
        Bs[acol + 0][arow] = bv.x; Bs[acol + 1][arow] = bv.y;
        Bs[acol + 2][arow] = bv.z; Bs[acol + 3][arow] = bv.w;
        __syncthreads();

#pragma unroll
        for (int kk = 0; kk < 16; kk++) {
            const float4 a = *(const float4*)&As[kk][ty * 4];
            const float4 b = *(const float4*)&Bs[kk][tx * 4];
            acc[0][0] += a.x * b.x; acc[0][1] += a.x * b.y;
            acc[0][2] += a.x * b.z; acc[0][3] += a.x * b.w;
            acc[1][0] += a.y * b.x; acc[1][1] += a.y * b.y;
            acc[1][2] += a.y * b.z; acc[1][3] += a.y * b.w;
            acc[2][0] += a.z * b.x; acc[2][1] += a.z * b.y;
            acc[2][2] += a.z * b.z; acc[2][3] += a.z * b.w;
            acc[3][0] += a.w * b.x; acc[3][1] += a.w * b.y;
            acc[3][2] += a.w * b.z; acc[3][3] += a.w * b.w;
        }
    }

#pragma unroll
    for (int i = 0; i < 4; i++) {
        const int r = mBase + ty * 4 + i;
        const bool keep = EPI_HAS ? (has[r] != 0) : true;
#pragma unroll
        for (int j = 0; j < 4; j++) {
            const int c = nBase + tx * 4 + j;
            float v = acc[i][j] + bias[c];
            if (EPI_HAS && !keep) v = 0.0f;
            C[(size_t)r * Nn + c] = v;
        }
    }
}

// ---------------------------------------------------------------------------
// Fused dual SGEMM: K = X @ W_k^T + b_k  AND  V = X @ W_v^T + b_v
// Shares the X (A-operand) smem tile between both products.
// Same 64x64x16 tiling, 256 threads, 4x4 microtile, two accumulator sets.
// ---------------------------------------------------------------------------
__global__ __launch_bounds__(256)
void sgemm_kv(const float* __restrict__ X,
              const float* __restrict__ Wk, const float* __restrict__ bk,
              const float* __restrict__ Wv, const float* __restrict__ bv,
              float* __restrict__ Kout, float* __restrict__ Vout)
{
    __shared__ float As[16][68];
    __shared__ float Ks[16][68];
    __shared__ float Vs[16][68];

    const int t     = threadIdx.x;
    const int mBase = blockIdx.y * 64;
    const int nBase = blockIdx.x * 64;

    const int arow = t >> 2;
    const int acol = (t & 3) * 4;

    const float* aptr  = X  + (size_t)(mBase + arow) * ADIM;
    const float* kptr  = Wk + (size_t)(nBase + arow) * ADIM;
    const float* vptr  = Wv + (size_t)(nBase + arow) * ADIM;

    const int tx = t & 15;
    const int ty = t >> 4;

    float accK[4][4] = {};
    float accV[4][4] = {};

    for (int k0 = 0; k0 < ADIM; k0 += 16) {
        const float4 av = *(const float4*)(aptr + k0 + acol);
        const float4 kv = *(const float4*)(kptr + k0 + acol);
        const float4 vv = *(const float4*)(vptr + k0 + acol);
        __syncthreads();
        As[acol + 0][arow] = av.x; As[acol + 1][arow] = av.y;
        As[acol + 2][arow] = av.z; As[acol + 3][arow] = av.w;
        Ks[acol + 0][arow] = kv.x; Ks[acol + 1][arow] = kv.y;
        Ks[acol + 2][arow] = kv.z; Ks[acol + 3][arow] = kv.w;
        Vs[acol + 0][arow] = vv.x; Vs[acol + 1][arow] = vv.y;
        Vs[acol + 2][arow] = vv.z; Vs[acol + 3][arow] = vv.w;
        __syncthreads();

#pragma unroll
        for (int kk = 0; kk < 16; kk++) {
            const float4 a = *(const float4*)&As[kk][ty * 4];
            const float4 b = *(const float4*)&Ks[kk][tx * 4];
            const float4 c = *(const float4*)&Vs[kk][tx * 4];
            accK[0][0] += a.x * b.x; accK[0][1] += a.x * b.y;
            accK[0][2] += a.x * b.z; accK[0][3] += a.x * b.w;
            accK[1][0] += a.y * b.x; accK[1][1] += a.y * b.y;
            accK[1][2] += a.y * b.z; accK[1][3] += a.y * b.w;
            accK[2][0] += a.z * b.x; accK[2][1] += a.z * b.y;
            accK[2][2] += a.z * b.z; accK[2][3] += a.z * b.w;
            accK[3][0] += a.w * b.x; accK[3][1] += a.w * b.y;
            accK[3][2] += a.w * b.z; accK[3][3] += a.w * b.w;
            accV[0][0] += a.x * c.x; accV[0][1] += a.x * c.y;
            accV[0][2] += a.x * c.z; accV[0][3] += a.x * c.w;
            accV[1][0] += a.y * c.x; accV[1][1] += a.y * c.y;
            accV[1][2] += a.y * c.z; accV[1][3] += a.y * c.w;
            accV[2][0] += a.z * c.x; accV[2][1] += a.z * c.y;
            accV[2][2] += a.z * c.z; accV[2][3] += a.z * c.w;
            accV[3][0] += a.w * c.x; accV[3][1] += a.w * c.y;
            accV[3][2] += a.w * c.z; accV[3][3] += a.w * c.w;
        }
    }

#pragma unroll
    for (int i = 0; i < 4; i++) {
        const size_t r = (size_t)(mBase + ty * 4 + i);
#pragma unroll
        for (int j = 0; j < 4; j++) {
            const int c = nBase + tx * 4 + j;
            Kout[r * ADIM + c] = accK[i][j] + bk[c];
            Vout[r * ADIM + c] = accV[i][j] + bv[c];
        }
    }
}

// ---------------------------------------------------------------------------
// Attention: one block per bn, one warp per head, lane = head-dim element.
// ---------------------------------------------------------------------------
__global__ __launch_bounds__(256)
void attn_kernel(const float* __restrict__ Km,
                 const float* __restrict__ Vm,
                 const float* __restrict__ query,
                 const int*   __restrict__ s2m,
                 const int*   __restrict__ s1m,
                 float*       __restrict__ CTX,
                 int*         __restrict__ hasArr)
{
    const int bn = blockIdx.x;
    const int h  = threadIdx.x >> 5;
    const int d  = threadIdx.x & 31;
    const float scale = 0.17677669529663687f;  // 32^-0.5

    const float qv = query[h * HD + d] * scale;

    float logits[NTOK];
    int anyEnc = 0;

#pragma unroll
    for (int n = 0; n < NTOK; n++) {
        const size_t idx = (size_t)(bn * NTOK + n) * ADIM + h * HD + d;
        float p = qv * Km[idx];
#pragma unroll
        for (int s = 16; s; s >>= 1)
            p += __shfl_xor_sync(0xffffffffu, p, s);
        const int mval = (n < 3) ? s2m[bn * 3 + n] : s1m[bn * 2 + (n - 3)];
        if (mval == 1) anyEnc = 1;
        logits[n] = (mval == 1) ? p : -1e30f;
    }

    float mx = logits[0];
#pragma unroll
    for (int n = 1; n < NTOK; n++) mx = fmaxf(mx, logits[n]);
    float wsum = 0.0f;
    float w[NTOK];
#pragma unroll
    for (int n = 0; n < NTOK; n++) { w[n] = expf(logits[n] - mx); wsum += w[n]; }
    const float inv = 1.0f / wsum;

    float acc = 0.0f;
#pragma unroll
    for (int n = 0; n < NTOK; n++) {
        const size_t idx = (size_t)(bn * NTOK + n) * ADIM + h * HD + d;
        acc += (w[n] * inv) * Vm[idx];
    }
    CTX[(size_t)bn * ADIM + h * HD + d] = acc;

    if (threadIdx.x == 0) hasArr[bn] = anyEnc;
}

// agg_mask tail (written as output dtype float)
__global__ void mask_tail_kernel(const int* __restrict__ has,
                                 float* __restrict__ out, int count)
{
    const int i = blockIdx.x * 256 + threadIdx.x;
    if (i < count) out[OUT_MAIN + i] = has[i] ? 1.0f : 0.0f;
}

// ---------------------------------------------------------------------------
extern "C" void kernel_launch(void* const* d_in, const int* in_sizes, int n_in,
                              void* d_out, int out_size)
{
    const float* s2    = (const float*)d_in[0];
    const float* s1    = (const float*)d_in[1];
    const float* W_in  = (const float*)d_in[2];
    const float* b_in  = (const float*)d_in[3];
    const float* W_k   = (const float*)d_in[4];
    const float* b_k   = (const float*)d_in[5];
    const float* W_v   = (const float*)d_in[6];
    const float* b_v   = (const float*)d_in[7];
    const float* W_out = (const float*)d_in[8];
    const float* b_out = (const float*)d_in[9];
    const float* query = (const float*)d_in[10];
    const int*   s2m   = (const int*)d_in[11];
    const int*   s1m   = (const int*)d_in[12];
    float* out = (float*)d_out;

    float *X, *Kb, *Vb, *CTX;
    int* has;
    cudaGetSymbolAddress((void**)&X,   g_X);
    cudaGetSymbolAddress((void**)&Kb,  g_K);
    cudaGetSymbolAddress((void**)&Vb,  g_V);
    cudaGetSymbolAddress((void**)&CTX, g_CTX);
    cudaGetSymbolAddress((void**)&has, g_has);

    dim3 blk(256);

    // 1) X = tokens @ W_in^T + b_in   (M=40960, N=256, K=768), gathered A
    {
        dim3 grid(ADIM / 64, ROWS / 64);
        sgemm_tn<true, false><<<grid, blk>>>(nullptr, s2, s1, W_in, b_in,
                                             nullptr, X, ROWS, ADIM, DDIM);
    }
    // 2+3) K,V = X @ {W_k,W_v}^T + {b_k,b_v}  (fused, shared A tiles)
    {
        dim3 grid(ADIM / 64, ROWS / 64);
        sgemm_kv<<<grid, blk>>>(X, W_k, b_k, W_v, b_v, Kb, Vb);
    }
    // 4) attention -> CTX, has flags
    attn_kernel<<<BN_TOT, blk>>>(Kb, Vb, query, s2m, s1m, CTX, has);

    // 5) OUT = CTX @ W_out^T + b_out, zero rows w/o encoder
    {
        dim3 grid(DDIM / 64, BN_TOT / 64);
        sgemm_tn<false, true><<<grid, blk>>>(CTX, nullptr, nullptr, W_out, b_out,
                                             has, out, BN_TOT, DDIM, ADIM);
    }

    // 6) agg_mask tail if the output buffer includes it
    const int extra = out_size - OUT_MAIN;
    if (extra > 0) {
        const int cnt = extra < BN_TOT ? extra : BN_TOT;
        mask_tail_kernel<<<(cnt + 255) / 256, 256>>>(has, out, cnt);
    }
}

// round 6
// speedup vs baseline: 2.0137x; 2.0137x over previous
#include <cuda_runtime.h>
#include <cuda_bf16.h>
#include <cstdint>
#include <math.h>

#define BN_TOT 8192
#define NTOK   5
#define ROWS   40960
#define DDIM   768
#define ADIM   256
#define NHEAD  8
#define HD     32
#define OUT_MAIN (BN_TOT * DDIM)

// Scratch (device globals: allocation-guard safe)
__device__ float g_X[ROWS * ADIM];
__device__ float g_K[ROWS * ADIM];
__device__ float g_V[ROWS * ADIM];
__device__ float g_CTX[BN_TOT * ADIM];
__device__ int   g_has[BN_TOT];

// bf16 split: hi = rn(v), lo = rn(v - hi). Residual <= 2^-16 * |v|.
__device__ __forceinline__ void split2(float x, float y,
                                       uint32_t& hi2, uint32_t& lo2) {
    __nv_bfloat16 hx = __float2bfloat16_rn(x);
    __nv_bfloat16 hy = __float2bfloat16_rn(y);
    __nv_bfloat16 lx = __float2bfloat16_rn(x - __bfloat162float(hx));
    __nv_bfloat16 ly = __float2bfloat16_rn(y - __bfloat162float(hy));
    __nv_bfloat162 h2; h2.x = hx; h2.y = hy;
    __nv_bfloat162 l2; l2.x = lx; l2.y = ly;
    hi2 = *reinterpret_cast<uint32_t*>(&h2);
    lo2 = *reinterpret_cast<uint32_t*>(&l2);
}

__device__ __forceinline__ void mma16816(float* c, const uint32_t* a,
                                         uint32_t b0, uint32_t b1) {
    asm volatile(
        "mma.sync.aligned.m16n8k16.row.col.f32.bf16.bf16.f32 "
        "{%0,%1,%2,%3}, {%4,%5,%6,%7}, {%8,%9}, {%0,%1,%2,%3};"
        : "+f"(c[0]), "+f"(c[1]), "+f"(c[2]), "+f"(c[3])
        : "r"(a[0]), "r"(a[1]), "r"(a[2]), "r"(a[3]), "r"(b0), "r"(b1));
}

// ---------------------------------------------------------------------------
// bf16-split tensor GEMM: C[M,N] = A[M,K] @ W[N,K]^T + bias (3-pass bf16).
// BM=128, BN=128, BK=32. 256 threads, 8 warps (4x2), warp tile 32x64.
// GATHER: A rows gathered from s2/s1. EPI_HAS: zero rows without encoder.
// DUAL: blockIdx.x >= halfX selects {W1,bias1,C1} (fused K/V projection).
// ---------------------------------------------------------------------------
#define SSTR 36   // smem row stride in bf16 elems (72B: conflict-free)

template<bool GATHER, bool EPI_HAS, bool DUAL>
__global__ __launch_bounds__(256)
void gemm_mma(const float* __restrict__ A,
              const float* __restrict__ s2, const float* __restrict__ s1,
              const float* __restrict__ W0, const float* __restrict__ bias0,
              const float* __restrict__ W1, const float* __restrict__ bias1,
              const int*   __restrict__ has,
              float* __restrict__ C0, float* __restrict__ C1,
              int Kk, int nChunks, int halfX, int Cstride)
{
    __shared__ __nv_bfloat16 sAh[128 * SSTR];
    __shared__ __nv_bfloat16 sAl[128 * SSTR];
    __shared__ __nv_bfloat16 sBh[128 * SSTR];
    __shared__ __nv_bfloat16 sBl[128 * SSTR];

    const int t = threadIdx.x;
    int bx = blockIdx.x;
    const float* W = W0; const float* bias = bias0; float* C = C0;
    if (DUAL && bx >= halfX) { W = W1; bias = bias1; C = C1; bx -= halfX; }
    const int mBase = blockIdx.y * 128;
    const int nBase = bx * 128;

    // Global-load assignments: 4 float4 per thread per tile (128x32 floats)
    const float* aPtr[4]; int aOff[4];
#pragma unroll
    for (int j = 0; j < 4; j++) {
        const int f = t + 256 * j;
        const int ar = f >> 3, ac4 = f & 7;
        const int grow = mBase + ar;
        const float* p;
        if (GATHER) {
            const int bn = grow / NTOK, nn = grow - bn * NTOK;
            p = (nn < 3) ? (s2 + (size_t)(bn * 3 + nn) * DDIM)
                         : (s1 + (size_t)(bn * 2 + (nn - 3)) * DDIM);
        } else {
            p = A + (size_t)grow * Kk;
        }
        aPtr[j] = p + ac4 * 4;
        aOff[j] = ar * SSTR + ac4 * 4;
    }
    const float* bPtr[4]; int bOff[4];
#pragma unroll
    for (int j = 0; j < 4; j++) {
        const int f = t + 256 * j;
        const int br = f >> 3, bc4 = f & 7;
        bPtr[j] = W + (size_t)(nBase + br) * Kk + bc4 * 4;
        bOff[j] = br * SSTR + bc4 * 4;
    }

    const int wid = t >> 5, lane = t & 31;
    const int mw = wid & 3, nw = wid >> 2;          // warp grid 4x2
    const int gid = lane >> 2, tg = lane & 3;
    const int mb0 = mw * 32;

    float acc[2][8][4];
#pragma unroll
    for (int f = 0; f < 2; f++)
#pragma unroll
        for (int j = 0; j < 8; j++)
#pragma unroll
            for (int q = 0; q < 4; q++) acc[f][j][q] = 0.0f;

    float4 av[4], bv[4];
#pragma unroll
    for (int j = 0; j < 4; j++) { av[j] = *(const float4*)aPtr[j]; bv[j] = *(const float4*)bPtr[j]; }

    for (int c = 0; c < nChunks; c++) {
        __syncthreads();   // prior compute done before smem overwrite
#pragma unroll
        for (int j = 0; j < 4; j++) {
            uint32_t h0, l0, h1, l1;
            split2(av[j].x, av[j].y, h0, l0);
            split2(av[j].z, av[j].w, h1, l1);
            *(uint32_t*)&sAh[aOff[j]]     = h0; *(uint32_t*)&sAh[aOff[j] + 2] = h1;
            *(uint32_t*)&sAl[aOff[j]]     = l0; *(uint32_t*)&sAl[aOff[j] + 2] = l1;
            split2(bv[j].x, bv[j].y, h0, l0);
            split2(bv[j].z, bv[j].w, h1, l1);
            *(uint32_t*)&sBh[bOff[j]]     = h0; *(uint32_t*)&sBh[bOff[j] + 2] = h1;
            *(uint32_t*)&sBl[bOff[j]]     = l0; *(uint32_t*)&sBl[bOff[j] + 2] = l1;
        }
        __syncthreads();

        if (c + 1 < nChunks) {
            const int k0 = (c + 1) * 32;
#pragma unroll
            for (int j = 0; j < 4; j++) {
                av[j] = *(const float4*)(aPtr[j] + k0);
                bv[j] = *(const float4*)(bPtr[j] + k0);
            }
        }

#pragma unroll
        for (int pass = 0; pass < 3; pass++) {
            const __nv_bfloat16* aS = (pass == 2) ? sAl : sAh;
            const __nv_bfloat16* bS = (pass == 1) ? sBl : sBh;
#pragma unroll
            for (int ks = 0; ks < 2; ks++) {
                uint32_t afr[2][4];
#pragma unroll
                for (int f = 0; f < 2; f++) {
                    const int base = (mb0 + f * 16 + gid) * SSTR + ks * 16 + tg * 2;
                    afr[f][0] = *(const uint32_t*)&aS[base];
                    afr[f][1] = *(const uint32_t*)&aS[base + 8 * SSTR];
                    afr[f][2] = *(const uint32_t*)&aS[base + 8];
                    afr[f][3] = *(const uint32_t*)&aS[base + 8 * SSTR + 8];
                }
#pragma unroll
                for (int j = 0; j < 8; j++) {
                    const int bbase = (nw * 64 + j * 8 + gid) * SSTR + ks * 16 + tg * 2;
                    const uint32_t b0 = *(const uint32_t*)&bS[bbase];
                    const uint32_t b1 = *(const uint32_t*)&bS[bbase + 8];
                    mma16816(acc[0][j], afr[0], b0, b1);
                    mma16816(acc[1][j], afr[1], b0, b1);
                }
            }
        }
    }

    // Epilogue: regs -> global with bias (+ has-mask)
#pragma unroll
    for (int f = 0; f < 2; f++) {
        const int r0 = mBase + mb0 + f * 16 + gid;
        const int r1 = r0 + 8;
        const bool k0 = EPI_HAS ? (__ldg(has + r0) != 0) : true;
        const bool k1 = EPI_HAS ? (__ldg(has + r1) != 0) : true;
#pragma unroll
        for (int j = 0; j < 8; j++) {
            const int col = nBase + nw * 64 + j * 8 + tg * 2;
            const float2 bb = *(const float2*)(bias + col);
            float2 o0, o1;
            o0.x = k0 ? (acc[f][j][0] + bb.x) : 0.0f;
            o0.y = k0 ? (acc[f][j][1] + bb.y) : 0.0f;
            o1.x = k1 ? (acc[f][j][2] + bb.x) : 0.0f;
            o1.y = k1 ? (acc[f][j][3] + bb.y) : 0.0f;
            *(float2*)(C + (size_t)r0 * Cstride + col) = o0;
            *(float2*)(C + (size_t)r1 * Cstride + col) = o1;
        }
    }
}

// ---------------------------------------------------------------------------
// Attention: one block per bn, one warp per head, lane = head-dim element.
// ---------------------------------------------------------------------------
__global__ __launch_bounds__(256)
void attn_kernel(const float* __restrict__ Km, const float* __restrict__ Vm,
                 const float* __restrict__ query,
                 const int* __restrict__ s2m, const int* __restrict__ s1m,
                 float* __restrict__ CTX, int* __restrict__ hasArr)
{
    const int bn = blockIdx.x;
    const int h  = threadIdx.x >> 5;
    const int d  = threadIdx.x & 31;
    const float scale = 0.17677669529663687f;  // 32^-0.5
    const float qv = query[h * HD + d] * scale;

    float logits[NTOK];
    int anyEnc = 0;
#pragma unroll
    for (int n = 0; n < NTOK; n++) {
        const size_t idx = (size_t)(bn * NTOK + n) * ADIM + h * HD + d;
        float p = qv * Km[idx];
#pragma unroll
        for (int s = 16; s; s >>= 1) p += __shfl_xor_sync(0xffffffffu, p, s);
        const int mval = (n < 3) ? s2m[bn * 3 + n] : s1m[bn * 2 + (n - 3)];
        if (mval == 1) anyEnc = 1;
        logits[n] = (mval == 1) ? p : -1e30f;
    }
    float mx = logits[0];
#pragma unroll
    for (int n = 1; n < NTOK; n++) mx = fmaxf(mx, logits[n]);
    float wsum = 0.0f, w[NTOK];
#pragma unroll
    for (int n = 0; n < NTOK; n++) { w[n] = expf(logits[n] - mx); wsum += w[n]; }
    const float inv = 1.0f / wsum;

    float acc = 0.0f;
#pragma unroll
    for (int n = 0; n < NTOK; n++) {
        const size_t idx = (size_t)(bn * NTOK + n) * ADIM + h * HD + d;
        acc += (w[n] * inv) * Vm[idx];
    }
    CTX[(size_t)bn * ADIM + h * HD + d] = acc;
    if (threadIdx.x == 0) hasArr[bn] = anyEnc;
}

__global__ void mask_tail_kernel(const int* __restrict__ has,
                                 float* __restrict__ out, int count)
{
    const int i = blockIdx.x * 256 + threadIdx.x;
    if (i < count) out[OUT_MAIN + i] = has[i] ? 1.0f : 0.0f;
}

// ---------------------------------------------------------------------------
extern "C" void kernel_launch(void* const* d_in, const int* in_sizes, int n_in,
                              void* d_out, int out_size)
{
    const float* s2    = (const float*)d_in[0];
    const float* s1    = (const float*)d_in[1];
    const float* W_in  = (const float*)d_in[2];
    const float* b_in  = (const float*)d_in[3];
    const float* W_k   = (const float*)d_in[4];
    const float* b_k   = (const float*)d_in[5];
    const float* W_v   = (const float*)d_in[6];
    const float* b_v   = (const float*)d_in[7];
    const float* W_out = (const float*)d_in[8];
    const float* b_out = (const float*)d_in[9];
    const float* query = (const float*)d_in[10];
    const int*   s2m   = (const int*)d_in[11];
    const int*   s1m   = (const int*)d_in[12];
    float* out = (float*)d_out;

    float *X, *Kb, *Vb, *CTX;
    int* has;
    cudaGetSymbolAddress((void**)&X,   g_X);
    cudaGetSymbolAddress((void**)&Kb,  g_K);
    cudaGetSymbolAddress((void**)&Vb,  g_V);
    cudaGetSymbolAddress((void**)&CTX, g_CTX);
    cudaGetSymbolAddress((void**)&has, g_has);

    dim3 blk(256);

    // 1) X = gather(tokens) @ W_in^T + b_in   (M=40960, N=256, K=768)
    gemm_mma<true, false, false><<<dim3(2, ROWS / 128), blk>>>(
        nullptr, s2, s1, W_in, b_in, nullptr, nullptr, nullptr,
        X, nullptr, DDIM, DDIM / 32, 0, ADIM);
    // 2+3) K,V = X @ {W_k,W_v}^T + {b_k,b_v}  (fused via DUAL)
    gemm_mma<false, false, true><<<dim3(4, ROWS / 128), blk>>>(
        X, nullptr, nullptr, W_k, b_k, W_v, b_v, nullptr,
        Kb, Vb, ADIM, ADIM / 32, 2, ADIM);
    // 4) attention -> CTX, has flags
    attn_kernel<<<BN_TOT, blk>>>(Kb, Vb, query, s2m, s1m, CTX, has);
    // 5) OUT = CTX @ W_out^T + b_out (N=768), zero rows w/o encoder
    gemm_mma<false, true, false><<<dim3(6, BN_TOT / 128), blk>>>(
        CTX, nullptr, nullptr, W_out, b_out, nullptr, nullptr, has,
        out, nullptr, ADIM, ADIM / 32, 0, DDIM);

    // 6) agg_mask tail if present in output buffer
    const int extra = out_size - OUT_MAIN;
    if (extra > 0) {
        const int cnt = extra < BN_TOT ? extra : BN_TOT;
        mask_tail_kernel<<<(cnt + 255) / 256, 256>>>(has, out, cnt);
    }
}